// round 9
// baseline (speedup 1.0000x reference)
#include <cuda_runtime.h>
#include <cuda_bf16.h>
#include <cstdint>

#define N_NODES 100000
#define N_EDGES 500000
#define NT_E 4            // edge tiles per CTA
#define NT_P 4            // node tiles per CTA

// Per-node layer-1 partials (bias folded): g_AB[n][0:128] = h@W1u^T + b1/2,
//                                          g_AB[n][128:256] = h@W1v^T + b1/2
__device__ float g_AB[(size_t)N_NODES * 256];

// B-operand fragment tables (mma.sync m16n8k16 B-fragment order, split bf16).
__device__ uint32_t g_w2frag[16384];   // [p][wn(4)][ks(8)][lane(32)][reg(8)]
__device__ uint32_t g_w1frag[32768];   // [p][ob(2)][wn(4)][ks(8)][lane(32)][reg(8)]

// Row-swizzled bf16 tile: 256B (128 bf16) per row; 16B chunks XORed by (row&7)
#define SW(row, cb) ((uint32_t)((row) * 256 + ((cb) ^ (((row) & 7) << 4))))

__device__ __forceinline__ uint32_t smem_u32(const void* p) {
    uint32_t a;
    asm("{ .reg .u64 t; cvta.to.shared.u64 t, %1; cvt.u32.u64 %0, t; }"
        : "=r"(a) : "l"(p));
    return a;
}
__device__ __forceinline__ void ldm_x4(uint32_t* r, uint32_t addr) {
    asm volatile("ldmatrix.sync.aligned.m8n8.x4.shared.b16 {%0,%1,%2,%3}, [%4];"
                 : "=r"(r[0]), "=r"(r[1]), "=r"(r[2]), "=r"(r[3]) : "r"(addr));
}
__device__ __forceinline__ void mma_bf16(float* d, const uint32_t* a,
                                         uint32_t b0, uint32_t b1) {
    asm volatile(
        "mma.sync.aligned.m16n8k16.row.col.f32.bf16.bf16.f32 "
        "{%0,%1,%2,%3}, {%4,%5,%6,%7}, {%8,%9}, {%0,%1,%2,%3};"
        : "+f"(d[0]), "+f"(d[1]), "+f"(d[2]), "+f"(d[3])
        : "r"(a[0]), "r"(a[1]), "r"(a[2]), "r"(a[3]), "r"(b0), "r"(b1));
}
__device__ __forceinline__ void split4(float4 v, uint2& hi, uint2& lo) {
    __nv_bfloat162 h01 = __floats2bfloat162_rn(v.x, v.y);
    __nv_bfloat162 h23 = __floats2bfloat162_rn(v.z, v.w);
    float r0 = v.x - __low2float(h01);
    float r1 = v.y - __high2float(h01);
    float r2 = v.z - __low2float(h23);
    float r3 = v.w - __high2float(h23);
    __nv_bfloat162 l01 = __floats2bfloat162_rn(r0, r1);
    __nv_bfloat162 l23 = __floats2bfloat162_rn(r2, r3);
    hi.x = *(uint32_t*)&h01; hi.y = *(uint32_t*)&h23;
    lo.x = *(uint32_t*)&l01; lo.y = *(uint32_t*)&l23;
}
__device__ __forceinline__ uint32_t split_pick(float v0, float v1, int p) {
    __nv_bfloat16 h0 = __float2bfloat16_rn(v0);
    __nv_bfloat16 h1 = __float2bfloat16_rn(v1);
    if (p) {
        h0 = __float2bfloat16_rn(v0 - __bfloat162float(h0));
        h1 = __float2bfloat16_rn(v1 - __bfloat162float(h1));
    }
    uint16_t a = *(uint16_t*)&h0, b = *(uint16_t*)&h1;
    return (uint32_t)a | ((uint32_t)b << 16);
}

// ---------------------------------------------------------------------------
__global__ void prep_frag_kernel(const float* __restrict__ W1,
                                 const float* __restrict__ W2)
{
    int idx = blockIdx.x * 256 + threadIdx.x;
    if (idx < 16384) {
        int r = idx & 7, lane = (idx >> 3) & 31, ks = (idx >> 8) & 7;
        int wn = (idx >> 11) & 3, p = (idx >> 13) & 1;
        int n = wn * 32 + (r >> 1) * 8 + (lane >> 2);
        int k = ks * 16 + (r & 1) * 8 + (lane & 3) * 2;
        const float* row = W2 + (size_t)n * 128;
        g_w2frag[idx] = split_pick(row[k], row[k + 1], p);
    } else if (idx < 16384 + 32768) {
        int j = idx - 16384;
        int r = j & 7, lane = (j >> 3) & 31, ks = (j >> 8) & 7;
        int wn = (j >> 11) & 3, ob = (j >> 13) & 1, p = (j >> 14) & 1;
        int go = ob * 128 + wn * 32 + (r >> 1) * 8 + (lane >> 2);
        int k = ks * 16 + (r & 1) * 8 + (lane & 3) * 2;
        const float* row = W1 + (size_t)(go & 127) * 256 + ((go >> 7) << 7);
        g_w1frag[j] = split_pick(row[k], row[k + 1], p);
    }
}

// ---------------------------------------------------------------------------
// MMA core: D[32 x 128-slice] += 3 split products. A from swizzled smem,
// B fragments from global tables (L1-resident LDG.128).
// ---------------------------------------------------------------------------
__device__ __forceinline__ void mma_core(float d[2][4][4],
                                         uint32_t xhi, uint32_t xlo,
                                         const uint4* wh, const uint4* wl,
                                         int wm, int lane)
{
    const int ar = wm * 32 + (lane & 15);
    const int kh = (lane >> 4) * 16;

    #pragma unroll
    for (int ks = 0; ks < 8; ks++) {
        const int kb = ks * 32 + kh;
        uint32_t ah[2][4], al[2][4];
        ldm_x4(ah[0], xhi + SW(ar, kb));
        ldm_x4(ah[1], xhi + SW(ar + 16, kb));
        ldm_x4(al[0], xlo + SW(ar, kb));
        ldm_x4(al[1], xlo + SW(ar + 16, kb));

        uint4 h0 = __ldg(wh + ks * 64), h1 = __ldg(wh + ks * 64 + 1);
        uint4 l0 = __ldg(wl + ks * 64), l1 = __ldg(wl + ks * 64 + 1);
        uint32_t bh[4][2] = {{h0.x, h0.y}, {h0.z, h0.w}, {h1.x, h1.y}, {h1.z, h1.w}};
        uint32_t bl[4][2] = {{l0.x, l0.y}, {l0.z, l0.w}, {l1.x, l1.y}, {l1.z, l1.w}};

        #pragma unroll
        for (int mt = 0; mt < 2; mt++)
            #pragma unroll
            for (int nt = 0; nt < 4; nt++)
                mma_bf16(d[mt][nt], ah[mt], bh[nt][0], bh[nt][1]);
        #pragma unroll
        for (int mt = 0; mt < 2; mt++)
            #pragma unroll
            for (int nt = 0; nt < 4; nt++)
                mma_bf16(d[mt][nt], ah[mt], bl[nt][0], bl[nt][1]);
        #pragma unroll
        for (int mt = 0; mt < 2; mt++)
            #pragma unroll
            for (int nt = 0; nt < 4; nt++)
                mma_bf16(d[mt][nt], al[mt], bh[nt][0], bh[nt][1]);
    }
}

// ---------------------------------------------------------------------------
// Precompute: NT_P node-tiles (64 nodes x 128 outs) per CTA, double-buffered
// fill(t+1) issued before mma(t). blockIdx low bit = out-half.
// ---------------------------------------------------------------------------
__global__ __launch_bounds__(256, 3) void precompute_kernel(
    const float* __restrict__ h, const float* __restrict__ b1)
{
    extern __shared__ char dyn[];
    char* base = (char*)(((uintptr_t)dyn + 1023) & ~(uintptr_t)1023);
    // buffer b: XHI = base + b*32768, XLO = +16384

    const int tid  = threadIdx.x;
    const int lane = tid & 31;
    const int wid  = tid >> 5;
    const int wm   = wid >> 2;
    const int wn   = wid & 3;
    const int ob   = (blockIdx.x & 1);
    const long tile0 = (long)(blockIdx.x >> 1) * NT_P;

    const int cb = lane * 8;
    const int fillBase = wm * 32 + wn * 8;

    auto fill = [&](int t, int b) {
        char* XH = base + b * 32768;
        char* XL = XH + 16384;
        long nb = (tile0 + t) * 64 + fillBase;
        #pragma unroll
        for (int i = 0; i < 8; i += 2) {
            long n0 = nb + i;     if (n0 >= N_NODES) n0 = N_NODES - 1;
            long n1 = nb + i + 1; if (n1 >= N_NODES) n1 = N_NODES - 1;
            float4 v0 = *(const float4*)(h + n0 * 128 + 4 * lane);
            float4 v1 = *(const float4*)(h + n1 * 128 + 4 * lane);
            uint2 hi0, lo0, hi1, lo1;
            split4(v0, hi0, lo0); split4(v1, hi1, lo1);
            uint32_t o0 = SW(fillBase + i, cb), o1 = SW(fillBase + i + 1, cb);
            *(uint2*)(XH + o0) = hi0; *(uint2*)(XL + o0) = lo0;
            *(uint2*)(XH + o1) = hi1; *(uint2*)(XL + o1) = lo1;
        }
    };

    fill(0, 0);
    asm volatile("bar.sync %0, 128;" :: "r"(wm + 1) : "memory");

    const uint4* wh = (const uint4*)(g_w1frag + ob * 8192 + wn * 2048) + lane * 2;
    const uint4* wl = (const uint4*)(g_w1frag + 16384 + ob * 8192 + wn * 2048) + lane * 2;

    const int bcol0 = wn * 32 + (lane & 3) * 2;
    float hb[4][2];
    #pragma unroll
    for (int nt = 0; nt < 4; nt++) {
        hb[nt][0] = 0.5f * __ldg(&b1[bcol0 + nt * 8]);
        hb[nt][1] = 0.5f * __ldg(&b1[bcol0 + nt * 8 + 1]);
    }
    const int oc = ob * 128 + bcol0;

    for (int t = 0; t < NT_P; t++) {
        const int curb = t & 1;
        if (t + 1 < NT_P) fill(t + 1, curb ^ 1);

        float d[2][4][4];
        #pragma unroll
        for (int mt = 0; mt < 2; mt++)
            #pragma unroll
            for (int nt = 0; nt < 4; nt++)
                #pragma unroll
                for (int i = 0; i < 4; i++) d[mt][nt][i] = 0.f;

        uint32_t xh = smem_u32(base + curb * 32768);
        mma_core(d, xh, xh + 16384, wh, wl, wm, lane);

        #pragma unroll
        for (int mt = 0; mt < 2; mt++) {
            #pragma unroll
            for (int rh = 0; rh < 2; rh++) {
                long n = (tile0 + t) * 64 + wm * 32 + mt * 16 + rh * 8 + (lane >> 2);
                if (n < N_NODES) {
                    float* orow = g_AB + n * 256 + oc;
                    #pragma unroll
                    for (int nt = 0; nt < 4; nt++) {
                        float2 v = make_float2(d[mt][nt][rh * 2]     + hb[nt][0],
                                               d[mt][nt][rh * 2 + 1] + hb[nt][1]);
                        *(float2*)(orow + nt * 8) = v;
                    }
                }
            }
        }
        asm volatile("bar.sync %0, 128;" :: "r"(wm + 1) : "memory");
    }
}

// ---------------------------------------------------------------------------
// Edge kernel: NT_E tiles (64 edges x 128 outs) per CTA, double-buffered.
// ---------------------------------------------------------------------------
__global__ __launch_bounds__(256, 3) void edge_kernel(
    const int* __restrict__ src, const int* __restrict__ dst,
    const float* __restrict__ b2, const float* __restrict__ W3,
    const float* __restrict__ b3, float* __restrict__ out)
{
    extern __shared__ char dyn[];
    char* base = (char*)(((uintptr_t)dyn + 1023) & ~(uintptr_t)1023);
    __shared__ float part[2][64][4];

    const int tid  = threadIdx.x;
    const int lane = tid & 31;
    const int wid  = tid >> 5;
    const int wm   = wid >> 2;
    const int wn   = wid & 3;
    const long tile0 = (long)blockIdx.x * NT_E;

    const int cb = lane * 8;
    const int fillBase = wm * 32 + wn * 8;

    auto fill = [&](int t, int b) {
        char* XH = base + b * 32768;
        char* XL = XH + 16384;
        long eb = (tile0 + t) * 64 + fillBase;
        int sidx[8], didx[8];
        #pragma unroll
        for (int i = 0; i < 8; i++) {
            long e = eb + i; if (e >= N_EDGES) e = N_EDGES - 1;
            sidx[i] = __ldg(&src[e]);
            didx[i] = __ldg(&dst[e]);
        }
        #pragma unroll
        for (int i = 0; i < 8; i += 2) {
            const float* a0p = g_AB + (size_t)sidx[i] * 256;
            const float* b0p = g_AB + (size_t)didx[i] * 256 + 128;
            const float* a1p = g_AB + (size_t)sidx[i + 1] * 256;
            const float* b1p = g_AB + (size_t)didx[i + 1] * 256 + 128;
            float4 a0 = *(const float4*)(a0p + 4 * lane);
            float4 b0 = *(const float4*)(b0p + 4 * lane);
            float4 a1 = *(const float4*)(a1p + 4 * lane);
            float4 b1v = *(const float4*)(b1p + 4 * lane);
            float4 x0, x1;
            x0.x = fmaxf(a0.x + b0.x, 0.f); x0.y = fmaxf(a0.y + b0.y, 0.f);
            x0.z = fmaxf(a0.z + b0.z, 0.f); x0.w = fmaxf(a0.w + b0.w, 0.f);
            x1.x = fmaxf(a1.x + b1v.x, 0.f); x1.y = fmaxf(a1.y + b1v.y, 0.f);
            x1.z = fmaxf(a1.z + b1v.z, 0.f); x1.w = fmaxf(a1.w + b1v.w, 0.f);
            uint2 hi0, lo0, hi1, lo1;
            split4(x0, hi0, lo0); split4(x1, hi1, lo1);
            uint32_t o0 = SW(fillBase + i, cb), o1 = SW(fillBase + i + 1, cb);
            *(uint2*)(XH + o0) = hi0; *(uint2*)(XL + o0) = lo0;
            *(uint2*)(XH + o1) = hi1; *(uint2*)(XL + o1) = lo1;
        }
    };

    fill(0, 0);
    asm volatile("bar.sync %0, 128;" :: "r"(wm + 1) : "memory");

    const uint4* wh = (const uint4*)(g_w2frag + wn * 2048) + lane * 2;
    const uint4* wl = (const uint4*)(g_w2frag + 8192 + wn * 2048) + lane * 2;

    const int o0c = wn * 32 + (lane & 3) * 2;
    float b2r[4][2], w3r[4][2];
    #pragma unroll
    for (int nt = 0; nt < 4; nt++) {
        b2r[nt][0] = __ldg(&b2[o0c + nt * 8]);
        b2r[nt][1] = __ldg(&b2[o0c + nt * 8 + 1]);
        w3r[nt][0] = __ldg(&W3[o0c + nt * 8]);
        w3r[nt][1] = __ldg(&W3[o0c + nt * 8 + 1]);
    }
    const float b3v = __ldg(&b3[0]);

    for (int t = 0; t < NT_E; t++) {
        const int curb = t & 1;
        if (t + 1 < NT_E) fill(t + 1, curb ^ 1);

        float d[2][4][4];
        #pragma unroll
        for (int nt = 0; nt < 4; nt++)
            #pragma unroll
            for (int mt = 0; mt < 2; mt++) {
                d[mt][nt][0] = b2r[nt][0]; d[mt][nt][1] = b2r[nt][1];
                d[mt][nt][2] = b2r[nt][0]; d[mt][nt][3] = b2r[nt][1];
            }

        uint32_t xh = smem_u32(base + curb * 32768);
        mma_core(d, xh, xh + 16384, wh, wl, wm, lane);

        // epilogue: relu + dot W3; quad reduce; stash (half-local)
        #pragma unroll
        for (int mt = 0; mt < 2; mt++) {
            #pragma unroll
            for (int rh = 0; rh < 2; rh++) {
                float p = 0.f;
                #pragma unroll
                for (int nt = 0; nt < 4; nt++) {
                    p = fmaf(w3r[nt][0], fmaxf(d[mt][nt][rh * 2],     0.f), p);
                    p = fmaf(w3r[nt][1], fmaxf(d[mt][nt][rh * 2 + 1], 0.f), p);
                }
                p += __shfl_xor_sync(0xffffffffu, p, 1);
                p += __shfl_xor_sync(0xffffffffu, p, 2);
                if ((lane & 3) == 0) {
                    int er = wm * 32 + mt * 16 + rh * 8 + (lane >> 2);
                    part[curb][er][wn] = p;
                }
            }
        }
        asm volatile("bar.sync %0, 128;" :: "r"(wm + 1) : "memory");

        if (wn == 0) {
            long e = (tile0 + t) * 64 + wm * 32 + lane;
            const float* pr = part[curb][wm * 32 + lane];
            if (e < N_EDGES)
                out[e] = pr[0] + pr[1] + pr[2] + pr[3] + b3v;
        }
    }
}

// ---------------------------------------------------------------------------
extern "C" void kernel_launch(void* const* d_in, const int* in_sizes, int n_in,
                              void* d_out, int out_size)
{
    const float* h   = (const float*)d_in[0];
    const int*   src = (const int*)  d_in[1];
    const int*   dst = (const int*)  d_in[2];
    const float* W1  = (const float*)d_in[3];
    const float* b1  = (const float*)d_in[4];
    const float* W2  = (const float*)d_in[5];
    const float* b2  = (const float*)d_in[6];
    const float* W3  = (const float*)d_in[7];
    const float* b3  = (const float*)d_in[8];
    float* out = (float*)d_out;

    const int smem_sz = 2 * 32768 + 1024;   // double-buffered X + align pad

    cudaFuncSetAttribute(precompute_kernel,
                         cudaFuncAttributeMaxDynamicSharedMemorySize, smem_sz);
    cudaFuncSetAttribute(edge_kernel,
                         cudaFuncAttributeMaxDynamicSharedMemorySize, smem_sz);

    int prepBlocks = (16384 + 32768 + 255) / 256;          // 192
    int nodeTiles  = (N_NODES + 63) / 64;                  // 1563
    int nodeBlocks = ((nodeTiles + NT_P - 1) / NT_P) * 2;  // 782
    int edgeTiles  = (N_EDGES + 63) / 64;                  // 7813
    int edgeBlocks = (edgeTiles + NT_E - 1) / NT_E;        // 1954

    prep_frag_kernel<<<prepBlocks, 256>>>(W1, W2);
    precompute_kernel<<<nodeBlocks, 256, smem_sz>>>(h, b1);
    edge_kernel<<<edgeBlocks, 256, smem_sz>>>(src, dst, b2, W3, b3, out);
}

// round 10
// speedup vs baseline: 1.1239x; 1.1239x over previous
#include <cuda_runtime.h>
#include <cuda_bf16.h>
#include <cstdint>

#define N_NODES 100000
#define N_EDGES 500000
#define NT_E 4            // edge tiles per CTA (64 edges each)
#define NT_P 4            // node tiles per CTA

__device__ float g_AB[(size_t)N_NODES * 256];

__device__ uint32_t g_w2frag[16384];   // [p][wn(4)][ks(8)][lane(32)][reg(8)]
__device__ uint32_t g_w1frag[32768];   // [p][ob(2)][wn(4)][ks(8)][lane(32)][reg(8)]

#define SW(row, cb) ((uint32_t)((row) * 256 + ((cb) ^ (((row) & 7) << 4))))

__device__ __forceinline__ uint32_t smem_u32(const void* p) {
    uint32_t a;
    asm("{ .reg .u64 t; cvta.to.shared.u64 t, %1; cvt.u32.u64 %0, t; }"
        : "=r"(a) : "l"(p));
    return a;
}
__device__ __forceinline__ void ldm_x4(uint32_t* r, uint32_t addr) {
    asm volatile("ldmatrix.sync.aligned.m8n8.x4.shared.b16 {%0,%1,%2,%3}, [%4];"
                 : "=r"(r[0]), "=r"(r[1]), "=r"(r[2]), "=r"(r[3]) : "r"(addr));
}
__device__ __forceinline__ void mma_bf16(float* d, const uint32_t* a,
                                         uint32_t b0, uint32_t b1) {
    asm volatile(
        "mma.sync.aligned.m16n8k16.row.col.f32.bf16.bf16.f32 "
        "{%0,%1,%2,%3}, {%4,%5,%6,%7}, {%8,%9}, {%0,%1,%2,%3};"
        : "+f"(d[0]), "+f"(d[1]), "+f"(d[2]), "+f"(d[3])
        : "r"(a[0]), "r"(a[1]), "r"(a[2]), "r"(a[3]), "r"(b0), "r"(b1));
}
__device__ __forceinline__ void split4(float4 v, uint2& hi, uint2& lo) {
    __nv_bfloat162 h01 = __floats2bfloat162_rn(v.x, v.y);
    __nv_bfloat162 h23 = __floats2bfloat162_rn(v.z, v.w);
    float r0 = v.x - __low2float(h01);
    float r1 = v.y - __high2float(h01);
    float r2 = v.z - __low2float(h23);
    float r3 = v.w - __high2float(h23);
    __nv_bfloat162 l01 = __floats2bfloat162_rn(r0, r1);
    __nv_bfloat162 l23 = __floats2bfloat162_rn(r2, r3);
    hi.x = *(uint32_t*)&h01; hi.y = *(uint32_t*)&h23;
    lo.x = *(uint32_t*)&l01; lo.y = *(uint32_t*)&l23;
}
__device__ __forceinline__ uint32_t split_pick(float v0, float v1, int p) {
    __nv_bfloat16 h0 = __float2bfloat16_rn(v0);
    __nv_bfloat16 h1 = __float2bfloat16_rn(v1);
    if (p) {
        h0 = __float2bfloat16_rn(v0 - __bfloat162float(h0));
        h1 = __float2bfloat16_rn(v1 - __bfloat162float(h1));
    }
    uint16_t a = *(uint16_t*)&h0, b = *(uint16_t*)&h1;
    return (uint32_t)a | ((uint32_t)b << 16);
}

// ---------------------------------------------------------------------------
__global__ void prep_frag_kernel(const float* __restrict__ W1,
                                 const float* __restrict__ W2)
{
    int idx = blockIdx.x * 256 + threadIdx.x;
    if (idx < 16384) {
        int r = idx & 7, lane = (idx >> 3) & 31, ks = (idx >> 8) & 7;
        int wn = (idx >> 11) & 3, p = (idx >> 13) & 1;
        int n = wn * 32 + (r >> 1) * 8 + (lane >> 2);
        int k = ks * 16 + (r & 1) * 8 + (lane & 3) * 2;
        const float* row = W2 + (size_t)n * 128;
        g_w2frag[idx] = split_pick(row[k], row[k + 1], p);
    } else if (idx < 16384 + 32768) {
        int j = idx - 16384;
        int r = j & 7, lane = (j >> 3) & 31, ks = (j >> 8) & 7;
        int wn = (j >> 11) & 3, ob = (j >> 13) & 1, p = (j >> 14) & 1;
        int go = ob * 128 + wn * 32 + (r >> 1) * 8 + (lane >> 2);
        int k = ks * 16 + (r & 1) * 8 + (lane & 3) * 2;
        const float* row = W1 + (size_t)(go & 127) * 256 + ((go >> 7) << 7);
        g_w1frag[j] = split_pick(row[k], row[k + 1], p);
    }
}

// ---------------------------------------------------------------------------
// MMA over ks range [k0, k1): D[32 x 128-slice] += 3 split products.
// ---------------------------------------------------------------------------
__device__ __forceinline__ void mma_range(float d[2][4][4],
                                          uint32_t xhi, uint32_t xlo,
                                          const uint4* wh, const uint4* wl,
                                          int wm, int lane, int k0, int k1)
{
    const int ar = wm * 32 + (lane & 15);
    const int kh = (lane >> 4) * 16;

    #pragma unroll
    for (int ks = k0; ks < k1; ks++) {
        const int kb = ks * 32 + kh;
        uint32_t ah[2][4], al[2][4];
        ldm_x4(ah[0], xhi + SW(ar, kb));
        ldm_x4(ah[1], xhi + SW(ar + 16, kb));
        ldm_x4(al[0], xlo + SW(ar, kb));
        ldm_x4(al[1], xlo + SW(ar + 16, kb));

        uint4 h0 = __ldg(wh + ks * 64), h1 = __ldg(wh + ks * 64 + 1);
        uint4 l0 = __ldg(wl + ks * 64), l1 = __ldg(wl + ks * 64 + 1);
        uint32_t bh[4][2] = {{h0.x, h0.y}, {h0.z, h0.w}, {h1.x, h1.y}, {h1.z, h1.w}};
        uint32_t bl[4][2] = {{l0.x, l0.y}, {l0.z, l0.w}, {l1.x, l1.y}, {l1.z, l1.w}};

        #pragma unroll
        for (int mt = 0; mt < 2; mt++)
            #pragma unroll
            for (int nt = 0; nt < 4; nt++)
                mma_bf16(d[mt][nt], ah[mt], bh[nt][0], bh[nt][1]);
        #pragma unroll
        for (int mt = 0; mt < 2; mt++)
            #pragma unroll
            for (int nt = 0; nt < 4; nt++)
                mma_bf16(d[mt][nt], ah[mt], bl[nt][0], bl[nt][1]);
        #pragma unroll
        for (int mt = 0; mt < 2; mt++)
            #pragma unroll
            for (int nt = 0; nt < 4; nt++)
                mma_bf16(d[mt][nt], al[mt], bh[nt][0], bh[nt][1]);
    }
}

// ---------------------------------------------------------------------------
// Precompute: NT_P tiles (64 nodes x 128 outs) per CTA, true pipeline:
// LDG(t+1) issued before mma(t), split+STS after. blockIdx low bit = out-half.
// ---------------------------------------------------------------------------
__global__ __launch_bounds__(256, 2) void precompute_kernel(
    const float* __restrict__ h, const float* __restrict__ b1)
{
    extern __shared__ char dyn[];
    char* base = (char*)(((uintptr_t)dyn + 1023) & ~(uintptr_t)1023);

    const int tid  = threadIdx.x;
    const int lane = tid & 31;
    const int wid  = tid >> 5;
    const int wm   = wid >> 2;
    const int wn   = wid & 3;
    const int ob   = (blockIdx.x & 1);
    const long node0 = (long)(blockIdx.x >> 1) * (NT_P * 64);

    const int cb = lane * 8;
    const int fillBase = wm * 32 + wn * 8;

    auto issue4 = [&](int t, int g, float4* S) {
        #pragma unroll
        for (int i = 0; i < 4; i++) {
            long n = node0 + t * 64 + fillBase + g * 4 + i;
            if (n >= N_NODES) n = N_NODES - 1;
            S[i] = *(const float4*)(h + n * 128 + 4 * lane);
        }
    };
    auto store4 = [&](int g, int b, const float4* S) {
        char* XH = base + b * 32768;
        char* XL = XH + 16384;
        #pragma unroll
        for (int i = 0; i < 4; i++) {
            uint2 hi, lo; split4(S[i], hi, lo);
            uint32_t o = SW(fillBase + g * 4 + i, cb);
            *(uint2*)(XH + o) = hi;
            *(uint2*)(XL + o) = lo;
        }
    };

    // prologue: tile 0 into buffer 0
    {
        float4 S[4];
        issue4(0, 0, S); store4(0, 0, S);
        issue4(0, 1, S); store4(1, 0, S);
    }
    asm volatile("bar.sync %0, 128;" :: "r"(wm + 1) : "memory");

    const uint4* wh = (const uint4*)(g_w1frag + ob * 8192 + wn * 2048) + lane * 2;
    const uint4* wl = (const uint4*)(g_w1frag + 16384 + ob * 8192 + wn * 2048) + lane * 2;

    const int bcol0 = wn * 32 + (lane & 3) * 2;
    float hb[4][2];
    #pragma unroll
    for (int nt = 0; nt < 4; nt++) {
        hb[nt][0] = 0.5f * __ldg(&b1[bcol0 + nt * 8]);
        hb[nt][1] = 0.5f * __ldg(&b1[bcol0 + nt * 8 + 1]);
    }
    const int oc = ob * 128 + bcol0;

    for (int t = 0; t < NT_P; t++) {
        const int curb = t & 1;
        const bool pf = (t + 1 < NT_P);
        uint32_t xh = smem_u32(base + curb * 32768);

        float4 S[4];
        if (pf) issue4(t + 1, 0, S);          // LDGs in flight...

        float d[2][4][4];
        #pragma unroll
        for (int mt = 0; mt < 2; mt++)
            #pragma unroll
            for (int nt = 0; nt < 4; nt++)
                #pragma unroll
                for (int i = 0; i < 4; i++) d[mt][nt][i] = 0.f;

        mma_range(d, xh, xh + 16384, wh, wl, wm, lane, 0, 4);   // ...hidden here
        if (pf) { store4(0, curb ^ 1, S); issue4(t + 1, 1, S); }
        mma_range(d, xh, xh + 16384, wh, wl, wm, lane, 4, 8);
        if (pf) store4(1, curb ^ 1, S);

        #pragma unroll
        for (int mt = 0; mt < 2; mt++) {
            #pragma unroll
            for (int rh = 0; rh < 2; rh++) {
                long n = node0 + t * 64 + wm * 32 + mt * 16 + rh * 8 + (lane >> 2);
                if (n < N_NODES) {
                    float* orow = g_AB + n * 256 + oc;
                    #pragma unroll
                    for (int nt = 0; nt < 4; nt++) {
                        float2 v = make_float2(d[mt][nt][rh * 2]     + hb[nt][0],
                                               d[mt][nt][rh * 2 + 1] + hb[nt][1]);
                        *(float2*)(orow + nt * 8) = v;
                    }
                }
            }
        }
        asm volatile("bar.sync %0, 128;" :: "r"(wm + 1) : "memory");
    }
}

// ---------------------------------------------------------------------------
// Edge kernel: NT_E tiles (64 edges x 128 outs) per CTA, true pipeline.
// All 256 edge indices staged to smem once in the prologue.
// ---------------------------------------------------------------------------
__global__ __launch_bounds__(256, 2) void edge_kernel(
    const int* __restrict__ src, const int* __restrict__ dst,
    const float* __restrict__ b2, const float* __restrict__ W3,
    const float* __restrict__ b3, float* __restrict__ out)
{
    extern __shared__ char dyn[];
    char* base = (char*)(((uintptr_t)dyn + 1023) & ~(uintptr_t)1023);
    __shared__ float part[2][64][4];
    __shared__ int sIdx[256], dIdx[256];

    const int tid  = threadIdx.x;
    const int lane = tid & 31;
    const int wid  = tid >> 5;
    const int wm   = wid >> 2;
    const int wn   = wid & 3;
    const long eCta = (long)blockIdx.x * (NT_E * 64);

    {
        long e = eCta + tid; if (e >= N_EDGES) e = N_EDGES - 1;
        sIdx[tid] = __ldg(&src[e]);
        dIdx[tid] = __ldg(&dst[e]);
    }
    __syncthreads();

    const int cb = lane * 8;
    const int fillBase = wm * 32 + wn * 8;

    auto issue4 = [&](int t, int g, float4* S) {
        #pragma unroll
        for (int i = 0; i < 4; i++) {
            int le = t * 64 + fillBase + g * 4 + i;   // local edge [0,256)
            const float* ap = g_AB + (size_t)sIdx[le] * 256;
            const float* bp = g_AB + (size_t)dIdx[le] * 256 + 128;
            S[2 * i]     = *(const float4*)(ap + 4 * lane);
            S[2 * i + 1] = *(const float4*)(bp + 4 * lane);
        }
    };
    auto store4 = [&](int g, int b, const float4* S) {
        char* XH = base + b * 32768;
        char* XL = XH + 16384;
        #pragma unroll
        for (int i = 0; i < 4; i++) {
            float4 a = S[2 * i], bb = S[2 * i + 1];
            float4 x;
            x.x = fmaxf(a.x + bb.x, 0.f); x.y = fmaxf(a.y + bb.y, 0.f);
            x.z = fmaxf(a.z + bb.z, 0.f); x.w = fmaxf(a.w + bb.w, 0.f);
            uint2 hi, lo; split4(x, hi, lo);
            uint32_t o = SW(fillBase + g * 4 + i, cb);
            *(uint2*)(XH + o) = hi;
            *(uint2*)(XL + o) = lo;
        }
    };

    // prologue: tile 0 into buffer 0
    {
        float4 S[8];
        issue4(0, 0, S); store4(0, 0, S);
        issue4(0, 1, S); store4(1, 0, S);
    }
    asm volatile("bar.sync %0, 128;" :: "r"(wm + 1) : "memory");

    const uint4* wh = (const uint4*)(g_w2frag + wn * 2048) + lane * 2;
    const uint4* wl = (const uint4*)(g_w2frag + 8192 + wn * 2048) + lane * 2;

    const int o0c = wn * 32 + (lane & 3) * 2;
    float b2r[4][2], w3r[4][2];
    #pragma unroll
    for (int nt = 0; nt < 4; nt++) {
        b2r[nt][0] = __ldg(&b2[o0c + nt * 8]);
        b2r[nt][1] = __ldg(&b2[o0c + nt * 8 + 1]);
        w3r[nt][0] = __ldg(&W3[o0c + nt * 8]);
        w3r[nt][1] = __ldg(&W3[o0c + nt * 8 + 1]);
    }
    const float b3v = __ldg(&b3[0]);

    for (int t = 0; t < NT_E; t++) {
        const int curb = t & 1;
        const bool pf = (t + 1 < NT_E);
        uint32_t xh = smem_u32(base + curb * 32768);

        float4 S[8];
        if (pf) issue4(t + 1, 0, S);          // LDGs in flight...

        float d[2][4][4];
        #pragma unroll
        for (int nt = 0; nt < 4; nt++)
            #pragma unroll
            for (int mt = 0; mt < 2; mt++) {
                d[mt][nt][0] = b2r[nt][0]; d[mt][nt][1] = b2r[nt][1];
                d[mt][nt][2] = b2r[nt][0]; d[mt][nt][3] = b2r[nt][1];
            }

        mma_range(d, xh, xh + 16384, wh, wl, wm, lane, 0, 4);   // ...hidden here
        if (pf) { store4(0, curb ^ 1, S); issue4(t + 1, 1, S); }
        mma_range(d, xh, xh + 16384, wh, wl, wm, lane, 4, 8);
        if (pf) store4(1, curb ^ 1, S);

        // epilogue: relu + dot W3; quad reduce; half-local stash
        #pragma unroll
        for (int mt = 0; mt < 2; mt++) {
            #pragma unroll
            for (int rh = 0; rh < 2; rh++) {
                float p = 0.f;
                #pragma unroll
                for (int nt = 0; nt < 4; nt++) {
                    p = fmaf(w3r[nt][0], fmaxf(d[mt][nt][rh * 2],     0.f), p);
                    p = fmaf(w3r[nt][1], fmaxf(d[mt][nt][rh * 2 + 1], 0.f), p);
                }
                p += __shfl_xor_sync(0xffffffffu, p, 1);
                p += __shfl_xor_sync(0xffffffffu, p, 2);
                if ((lane & 3) == 0) {
                    int er = wm * 32 + mt * 16 + rh * 8 + (lane >> 2);
                    part[curb][er][wn] = p;
                }
            }
        }
        asm volatile("bar.sync %0, 128;" :: "r"(wm + 1) : "memory");

        if (wn == 0) {
            long e = eCta + t * 64 + wm * 32 + lane;
            const float* pr = part[curb][wm * 32 + lane];
            if (e < N_EDGES)
                out[e] = pr[0] + pr[1] + pr[2] + pr[3] + b3v;
        }
    }
}

// ---------------------------------------------------------------------------
extern "C" void kernel_launch(void* const* d_in, const int* in_sizes, int n_in,
                              void* d_out, int out_size)
{
    const float* h   = (const float*)d_in[0];
    const int*   src = (const int*)  d_in[1];
    const int*   dst = (const int*)  d_in[2];
    const float* W1  = (const float*)d_in[3];
    const float* b1  = (const float*)d_in[4];
    const float* W2  = (const float*)d_in[5];
    const float* b2  = (const float*)d_in[6];
    const float* W3  = (const float*)d_in[7];
    const float* b3  = (const float*)d_in[8];
    float* out = (float*)d_out;

    const int smem_sz = 2 * 32768 + 1024;   // double-buffered X + align pad

    cudaFuncSetAttribute(precompute_kernel,
                         cudaFuncAttributeMaxDynamicSharedMemorySize, smem_sz);
    cudaFuncSetAttribute(edge_kernel,
                         cudaFuncAttributeMaxDynamicSharedMemorySize, smem_sz);

    int prepBlocks = (16384 + 32768 + 255) / 256;          // 192
    int nodeTiles  = (N_NODES + 63) / 64;                  // 1563
    int nodeBlocks = ((nodeTiles + NT_P - 1) / NT_P) * 2;  // 782
    int edgeTiles  = (N_EDGES + 63) / 64;                  // 7813
    int edgeBlocks = (edgeTiles + NT_E - 1) / NT_E;        // 1954

    prep_frag_kernel<<<prepBlocks, 256>>>(W1, W2);
    precompute_kernel<<<nodeBlocks, 256, smem_sz>>>(h, b1);
    edge_kernel<<<edgeBlocks, 256, smem_sz>>>(src, dst, b2, W3, b3, out);
}